// round 5
// baseline (speedup 1.0000x reference)
#include <cuda_runtime.h>
#include <cstdint>
#include <math.h>
#include <float.h>

// Problem constants
#define B_SZ 128
#define C_SZ 1024
#define D_SZ 32000           // 8*250*16
#define D4   (D_SZ/4)
#define TOPK 5
#define TEMP 0.1f

// GEMM structure: K atoms of 32, split-K
#define BKA    32
#define NATOMS (D_SZ / BKA)   // 1000
#define SPLITS 18             // 8 * 18 = 144 CTAs = 1 wave
#define NB     8              // N tiles of 128

// smem: pitch 36 floats (144B rows: 16B-aligned, odd # of 16B granules -> conflict-free)
#define PT 36
#define FB_TILE_FLOATS (128 * PT)         // 4608 floats = 18432 B
#define DYN_SMEM (4 * FB_TILE_FLOATS * 4) // 73728 B

// Output layout (float32): quantized | main_indices | main_distances | usage_new
#define OFF_Q     0
#define OFF_IDX   (B_SZ * D_SZ)
#define OFF_DIST  (OFF_IDX + B_SZ)
#define OFF_USAGE (OFF_DIST + B_SZ)

// Scratch (device globals — no allocation allowed)
__device__ float g_part[SPLITS][B_SZ * C_SZ];   // 9.4 MB split-K partial dots
__device__ float g_cnp[SPLITS][C_SZ];           // codebook norm partials
__device__ float g_lnp[SPLITS][B_SZ];           // latent norm partials
__device__ float g_topw[B_SZ][8];
__device__ int   g_topi[B_SZ][8];

// ---------------------------------------------------------------------------
// Helpers
// ---------------------------------------------------------------------------
__device__ __forceinline__ uint32_t smem_u32(const void* p) {
    uint32_t a;
    asm("{ .reg .u64 t; cvta.to.shared.u64 t, %1; cvt.u32.u64 %0, t; }" : "=r"(a) : "l"(p));
    return a;
}
__device__ __forceinline__ void unpack2(unsigned long long v, float& x, float& y) {
    asm("mov.b64 {%0, %1}, %2;" : "=f"(x), "=f"(y) : "l"(v));
}
__device__ __forceinline__ void ffma2(unsigned long long& d,
                                      unsigned long long a,
                                      unsigned long long b) {
    asm("fma.rn.f32x2 %0, %1, %2, %3;" : "=l"(d) : "l"(a), "l"(b), "l"(d));
}
__device__ __forceinline__ void cpasync16(uint32_t dst, const void* src) {
    asm volatile("cp.async.cg.shared.global [%0], [%1], 16;"
                 :: "r"(dst), "l"(src) : "memory");
}
#define CP_COMMIT() asm volatile("cp.async.commit_group;" ::: "memory")
#define CP_WAIT1()  asm volatile("cp.async.wait_group 1;" ::: "memory")

// ---------------------------------------------------------------------------
// Split-K GEMM, FFMA2 k-pair inner loop, cp.async double-buffered loads,
// fused codebook + latent norms, usage copy in block (0,0).
// grid = (NB, SPLITS), 256 threads.
// ---------------------------------------------------------------------------
__global__ __launch_bounds__(256, 1)
void gemm_kernel(const float* __restrict__ A,   // latent  [128][32000]
                 const float* __restrict__ Bm,  // codebook[1024][32000]
                 const float* __restrict__ usage_in,
                 float* __restrict__ usage_out)
{
    extern __shared__ float dynf[];
    float* As0 = dynf;
    float* As1 = dynf + FB_TILE_FLOATS;
    float* Bs0 = dynf + 2 * FB_TILE_FLOATS;
    float* Bs1 = dynf + 3 * FB_TILE_FLOATS;

    const int t  = threadIdx.x;
    const int bx = blockIdx.x;
    const int s  = blockIdx.y;
    const int n0 = bx * 128;
    // uneven split: 1000 atoms = 18*55 + 10; splits 0..9 get 56
    const int tile0 = s * 55 + min(s, 10);
    const int ntile = 55 + (s < 10 ? 1 : 0);

    // usage copy (ordered before topk's atomics by kernel ordering)
    if (bx == 0 && s == 0)
        ((float4*)usage_out)[t] = ((const float4*)usage_in)[t];

    const int row  = t >> 1;
    const int half = t & 1;
    const int ty   = t >> 4;
    const int tx   = t & 15;

    const float* aSrc = A  + (size_t)row * D_SZ + half * 16;
    const float* bSrc = Bm + (size_t)(n0 + row) * D_SZ + half * 16;

    const uint32_t asU0 = smem_u32(As0);
    const uint32_t asU1 = smem_u32(As1);
    const uint32_t bsU0 = smem_u32(Bs0);
    const uint32_t bsU1 = smem_u32(Bs1);
    const uint32_t off  = (uint32_t)(row * PT + half * 16) * 4u;

    unsigned long long acc[8][8];
#pragma unroll
    for (int i = 0; i < 8; i++)
#pragma unroll
        for (int j = 0; j < 8; j++) acc[i][j] = 0ULL;

    unsigned long long nb2 = 0ULL, na2 = 0ULL;

    // prologue: issue group 0
    {
        const float* sa = aSrc + (size_t)tile0 * BKA;
        const float* sb = bSrc + (size_t)tile0 * BKA;
#pragma unroll
        for (int q = 0; q < 4; q++) cpasync16(asU0 + off + q * 16, sa + q * 4);
#pragma unroll
        for (int q = 0; q < 4; q++) cpasync16(bsU0 + off + q * 16, sb + q * 4);
        CP_COMMIT();
    }

    for (int it = 0; it < ntile; it++) {
        const int st = it & 1;
        // issue group it+1
        if (it + 1 < ntile) {
            const float* sa = aSrc + (size_t)(tile0 + it + 1) * BKA;
            const float* sb = bSrc + (size_t)(tile0 + it + 1) * BKA;
            const uint32_t ad = ((it + 1) & 1) ? asU1 : asU0;
            const uint32_t bd = ((it + 1) & 1) ? bsU1 : bsU0;
#pragma unroll
            for (int q = 0; q < 4; q++) cpasync16(ad + off + q * 16, sa + q * 4);
#pragma unroll
            for (int q = 0; q < 4; q++) cpasync16(bd + off + q * 16, sb + q * 4);
        }
        CP_COMMIT();
        CP_WAIT1();              // group it complete (group it+1 may be pending)
        __syncthreads();

        const float* as = st ? As1 : As0;
        const float* bs = st ? Bs1 : Bs0;

        // fused norms from smem (conflict-free: 144B row stride)
        {
            const float* br = bs + row * PT + half * 16;
            ulonglong2 p0 = *(const ulonglong2*)(br);
            ulonglong2 p1 = *(const ulonglong2*)(br + 4);
            ulonglong2 p2 = *(const ulonglong2*)(br + 8);
            ulonglong2 p3 = *(const ulonglong2*)(br + 12);
            ffma2(nb2, p0.x, p0.x); ffma2(nb2, p0.y, p0.y);
            ffma2(nb2, p1.x, p1.x); ffma2(nb2, p1.y, p1.y);
            ffma2(nb2, p2.x, p2.x); ffma2(nb2, p2.y, p2.y);
            ffma2(nb2, p3.x, p3.x); ffma2(nb2, p3.y, p3.y);
            if (bx == 0) {
                const float* ar = as + row * PT + half * 16;
                ulonglong2 q0 = *(const ulonglong2*)(ar);
                ulonglong2 q1 = *(const ulonglong2*)(ar + 4);
                ulonglong2 q2 = *(const ulonglong2*)(ar + 8);
                ulonglong2 q3 = *(const ulonglong2*)(ar + 12);
                ffma2(na2, q0.x, q0.x); ffma2(na2, q0.y, q0.y);
                ffma2(na2, q1.x, q1.x); ffma2(na2, q1.y, q1.y);
                ffma2(na2, q2.x, q2.x); ffma2(na2, q2.y, q2.y);
                ffma2(na2, q3.x, q3.x); ffma2(na2, q3.y, q3.y);
            }
        }

#pragma unroll
        for (int k4 = 0; k4 < 8; k4++) {
            ulonglong2 a2[8];
#pragma unroll
            for (int i = 0; i < 8; i++)
                a2[i] = *(const ulonglong2*)(as + (ty + 16 * i) * PT + k4 * 4);
            ulonglong2 b2[4];
#pragma unroll
            for (int j = 0; j < 4; j++)
                b2[j] = *(const ulonglong2*)(bs + (tx + 16 * j) * PT + k4 * 4);
#pragma unroll
            for (int i = 0; i < 8; i++)
#pragma unroll
                for (int j = 0; j < 4; j++) ffma2(acc[i][j], a2[i].x, b2[j].x);
#pragma unroll
            for (int i = 0; i < 8; i++)
#pragma unroll
                for (int j = 0; j < 4; j++) ffma2(acc[i][j], a2[i].y, b2[j].y);
#pragma unroll
            for (int j = 0; j < 4; j++)
                b2[j] = *(const ulonglong2*)(bs + (tx + 16 * (j + 4)) * PT + k4 * 4);
#pragma unroll
            for (int i = 0; i < 8; i++)
#pragma unroll
                for (int j = 0; j < 4; j++) ffma2(acc[i][j + 4], a2[i].x, b2[j].x);
#pragma unroll
            for (int i = 0; i < 8; i++)
#pragma unroll
                for (int j = 0; j < 4; j++) ffma2(acc[i][j + 4], a2[i].y, b2[j].y);
        }
        __syncthreads();
    }

    // norm writeout: thread pair (2r,2r+1) owns row r
    {
        float lo, hi;
        unpack2(nb2, lo, hi);
        float nb = lo + hi;
        nb += __shfl_xor_sync(0xFFFFFFFFu, nb, 1);
        if (half == 0) g_cnp[s][n0 + row] = nb;
        if (bx == 0) {
            unpack2(na2, lo, hi);
            float na = lo + hi;
            na += __shfl_xor_sync(0xFFFFFFFFu, na, 1);
            if (half == 0) g_lnp[s][row] = na;
        }
    }

    // result writeout: fold lo+hi (k-even / k-odd partial sums)
    float* op = g_part[s];
#pragma unroll
    for (int i = 0; i < 8; i++) {
        const int m = ty + 16 * i;
#pragma unroll
        for (int j = 0; j < 8; j++) {
            float lo, hi;
            unpack2(acc[i][j], lo, hi);
            op[(size_t)m * C_SZ + n0 + tx + 16 * j] = lo + hi;
        }
    }
}

// ---------------------------------------------------------------------------
// Per-row: reduce partials (+ inline norm sums) -> dist, top-5 (lowest-index
// tie-break), softmax, outputs, usage scatter-add, stash for quantize.
// ---------------------------------------------------------------------------
__global__ void topk_kernel(float* __restrict__ out) {
    const int b   = blockIdx.x;
    const int tid = threadIdx.x;

    __shared__ float sd[C_SZ];
    __shared__ float rv[256];
    __shared__ int   ri[256];
    __shared__ float topd[TOPK];
    __shared__ int   topi[TOPK];
    __shared__ float s_ln;

    if (tid == 0) {
        float v = 0.f;
#pragma unroll
        for (int s = 0; s < SPLITS; s++) v += g_lnp[s][b];
        s_ln = v;
    }
    __syncthreads();
    const float ln = s_ln;

    for (int c = tid; c < C_SZ; c += 256) {
        float dot = 0.f, cn = 0.f;
#pragma unroll
        for (int s = 0; s < SPLITS; s++) {
            dot += g_part[s][b * C_SZ + c];
            cn  += g_cnp[s][c];
        }
        float d2 = ln + cn - 2.f * dot;
        sd[c] = sqrtf(fmaxf(d2, 0.f));
    }
    __syncthreads();

    for (int k = 0; k < TOPK; k++) {
        float best = FLT_MAX;
        int   bi   = C_SZ;
        for (int c = tid; c < C_SZ; c += 256) {
            float d = sd[c];
            if (d < best || (d == best && c < bi)) { best = d; bi = c; }
        }
        rv[tid] = best; ri[tid] = bi;
        __syncthreads();
        for (int s = 128; s > 0; s >>= 1) {
            if (tid < s) {
                float o = rv[tid + s]; int oi = ri[tid + s];
                if (o < rv[tid] || (o == rv[tid] && oi < ri[tid])) {
                    rv[tid] = o; ri[tid] = oi;
                }
            }
            __syncthreads();
        }
        if (tid == 0) {
            topd[k] = rv[0];
            topi[k] = ri[0];
            sd[ri[0]] = FLT_MAX;
        }
        __syncthreads();
    }

    if (tid == 0) {
        float m0 = topd[0];
        float e[TOPK], ssum = 0.f;
#pragma unroll
        for (int k = 0; k < TOPK; k++) {
            e[k] = expf(-(topd[k] - m0) / TEMP);
            ssum += e[k];
        }
        float inv = 1.f / ssum;
        out[OFF_IDX  + b] = (float)topi[0];
        out[OFF_DIST + b] = topd[0];
#pragma unroll
        for (int k = 0; k < TOPK; k++) {
            float w = e[k] * inv;
            atomicAdd(&out[OFF_USAGE + topi[k]], w);
            g_topw[b][k] = w;
            g_topi[b][k] = topi[k];
        }
    }
}

// ---------------------------------------------------------------------------
// quantized[b] = sum_k w[b][k] * codebook[idx[b][k]]   grid (B, 16 chunks)
// ---------------------------------------------------------------------------
__global__ void quant_kernel(const float* __restrict__ codebook,
                             float* __restrict__ out) {
    const int b     = blockIdx.x;
    const int chunk = blockIdx.y;
    const int tid   = threadIdx.x;
    __shared__ int   si[TOPK];
    __shared__ float sw[TOPK];
    if (tid < TOPK) { si[tid] = g_topi[b][tid]; sw[tid] = g_topw[b][tid]; }
    __syncthreads();

    const float4* cb = (const float4*)codebook;
    float4* outq = (float4*)(out + OFF_Q) + (size_t)b * D4;

    const float4* r0 = cb + (size_t)si[0] * D4;
    const float4* r1 = cb + (size_t)si[1] * D4;
    const float4* r2 = cb + (size_t)si[2] * D4;
    const float4* r3 = cb + (size_t)si[3] * D4;
    const float4* r4 = cb + (size_t)si[4] * D4;
    const float w0 = sw[0], w1 = sw[1], w2 = sw[2], w3 = sw[3], w4 = sw[4];

    const int p0 = chunk * (D4 / 16);
    const int p1 = p0 + (D4 / 16);
    for (int p = p0 + tid; p < p1; p += 256) {
        float4 v0 = r0[p], v1 = r1[p], v2 = r2[p], v3 = r3[p], v4 = r4[p];
        float4 r;
        r.x = w0 * v0.x + w1 * v1.x + w2 * v2.x + w3 * v3.x + w4 * v4.x;
        r.y = w0 * v0.y + w1 * v1.y + w2 * v2.y + w3 * v3.y + w4 * v4.y;
        r.z = w0 * v0.z + w1 * v1.z + w2 * v2.z + w3 * v3.z + w4 * v4.z;
        r.w = w0 * v0.w + w1 * v1.w + w2 * v2.w + w3 * v3.w + w4 * v4.w;
        outq[p] = r;
    }
}

// ---------------------------------------------------------------------------
extern "C" void kernel_launch(void* const* d_in, const int* in_sizes, int n_in,
                              void* d_out, int out_size) {
    const float* latent   = (const float*)d_in[0];
    const float* codebook = (const float*)d_in[1];
    const float* usage    = (const float*)d_in[2];
    float* out = (float*)d_out;

    cudaFuncSetAttribute((const void*)gemm_kernel,
                         cudaFuncAttributeMaxDynamicSharedMemorySize, DYN_SMEM);
    gemm_kernel<<<dim3(NB, SPLITS), 256, DYN_SMEM>>>(latent, codebook,
                                                     usage, out + OFF_USAGE);
    topk_kernel<<<B_SZ, 256>>>(out);
    quant_kernel<<<dim3(B_SZ, 16), 256>>>(codebook, out);
}

// round 6
// speedup vs baseline: 1.0229x; 1.0229x over previous
#include <cuda_runtime.h>
#include <cstdint>
#include <math.h>
#include <float.h>

// Problem constants
#define B_SZ 128
#define C_SZ 1024
#define D_SZ 32000           // 8*250*16
#define D4   (D_SZ/4)
#define TOPK 5
#define TEMP 0.1f

// GEMM structure: K atoms of 32, split-K
#define BKA    32
#define SPLITS 18             // 8 * 18 = 144 CTAs = 1 wave
#define NB     8              // N tiles of 128

// smem: pitch 36 floats (144B rows: 16B-aligned, odd # of 16B granules -> conflict-free)
#define PT 36
#define FB_TILE_FLOATS (128 * PT)         // 4608 floats = 18432 B
#define DYN_SMEM (4 * FB_TILE_FLOATS * 4) // 73728 B

// Output layout (float32): quantized | main_indices | main_distances | usage_new
#define OFF_Q     0
#define OFF_IDX   (B_SZ * D_SZ)
#define OFF_DIST  (OFF_IDX + B_SZ)
#define OFF_USAGE (OFF_DIST + B_SZ)

// Scratch (device globals — no allocation allowed)
__device__ float g_part[SPLITS][B_SZ * C_SZ];   // 9.4 MB split-K partial dots
__device__ float g_cnp[SPLITS][C_SZ];           // codebook norm partials
__device__ float g_lnp[SPLITS][B_SZ];           // latent norm partials
__device__ float g_topw[B_SZ][8];
__device__ int   g_topi[B_SZ][8];

// ---------------------------------------------------------------------------
// Helpers
// ---------------------------------------------------------------------------
__device__ __forceinline__ uint32_t smem_u32(const void* p) {
    uint32_t a;
    asm("{ .reg .u64 t; cvta.to.shared.u64 t, %1; cvt.u32.u64 %0, t; }" : "=r"(a) : "l"(p));
    return a;
}
__device__ __forceinline__ void unpack2(unsigned long long v, float& x, float& y) {
    asm("mov.b64 {%0, %1}, %2;" : "=f"(x), "=f"(y) : "l"(v));
}
__device__ __forceinline__ void ffma2(unsigned long long& d,
                                      unsigned long long a,
                                      unsigned long long b) {
    asm("fma.rn.f32x2 %0, %1, %2, %3;" : "=l"(d) : "l"(a), "l"(b), "l"(d));
}
__device__ __forceinline__ void cpasync16(uint32_t dst, const void* src) {
    asm volatile("cp.async.cg.shared.global [%0], [%1], 16;"
                 :: "r"(dst), "l"(src) : "memory");
}
#define CP_COMMIT() asm volatile("cp.async.commit_group;" ::: "memory")
#define CP_WAIT0()  asm volatile("cp.async.wait_group 0;" ::: "memory")

// ---------------------------------------------------------------------------
// Split-K GEMM (R4 structure + single sync per tile).
// A via cp.async (depth-1), B via LDG->reg prefetch->STS, norms fused.
// grid = (NB, SPLITS), 256 threads.
// ---------------------------------------------------------------------------
__global__ __launch_bounds__(256, 1)
void gemm_kernel(const float* __restrict__ A,   // latent  [128][32000]
                 const float* __restrict__ Bm,  // codebook[1024][32000]
                 const float* __restrict__ usage_in,
                 float* __restrict__ usage_out)
{
    extern __shared__ float dynf[];
    float* As0 = dynf;
    float* As1 = dynf + FB_TILE_FLOATS;
    float* Bs0 = dynf + 2 * FB_TILE_FLOATS;
    float* Bs1 = dynf + 3 * FB_TILE_FLOATS;

    const int t  = threadIdx.x;
    const int bx = blockIdx.x;
    const int s  = blockIdx.y;
    const int n0 = bx * 128;
    // uneven split: 1000 atoms = 18*55 + 10; splits 0..9 get 56
    const int tile0 = s * 55 + min(s, 10);
    const int ntile = 55 + (s < 10 ? 1 : 0);

    // usage copy (ordered before topk's atomics by kernel ordering)
    if (bx == 0 && s == 0)
        ((float4*)usage_out)[t] = ((const float4*)usage_in)[t];

    const int row  = t >> 1;
    const int half = t & 1;
    const int ty   = t >> 4;
    const int tx   = t & 15;

    const float* aSrc = A  + (size_t)row * D_SZ + half * 16;
    const float* bSrc = Bm + (size_t)(n0 + row) * D_SZ + half * 16;

    const uint32_t asU0 = smem_u32(As0);
    const uint32_t asU1 = smem_u32(As1);
    const uint32_t off  = (uint32_t)(row * PT + half * 16) * 4u;

    unsigned long long acc[8][8];
#pragma unroll
    for (int i = 0; i < 8; i++)
#pragma unroll
        for (int j = 0; j < 8; j++) acc[i][j] = 0ULL;

    unsigned long long nb2 = 0ULL, na2 = 0ULL;
    float4 bv[4];

    // ---- prologue: stage tile0 into buffer 0 ----
    {
        const float4* bp4 = (const float4*)(bSrc + (size_t)tile0 * BKA);
#pragma unroll
        for (int q = 0; q < 4; q++) bv[q] = bp4[q];
        const float* sa = aSrc + (size_t)tile0 * BKA;
#pragma unroll
        for (int q = 0; q < 4; q++) cpasync16(asU0 + off + q * 16, sa + q * 4);
        CP_COMMIT();
        CP_WAIT0();
        float* bs = Bs0 + row * PT + half * 16;
#pragma unroll
        for (int q = 0; q < 4; q++) {
            ulonglong2 u = *(const ulonglong2*)&bv[q];
            ffma2(nb2, u.x, u.x); ffma2(nb2, u.y, u.y);
            *(float4*)(bs + q * 4) = bv[q];
        }
        __syncthreads();
    }

    for (int it = 0; it < ntile; it++) {
        const int st = it & 1;
        const bool more = (it + 1 < ntile);

        // issue next tile's loads early: B -> regs, A -> cp.async (to buf st^1)
        if (more) {
            const float4* bp4 = (const float4*)(bSrc + (size_t)(tile0 + it + 1) * BKA);
#pragma unroll
            for (int q = 0; q < 4; q++) bv[q] = bp4[q];
            const float* sa = aSrc + (size_t)(tile0 + it + 1) * BKA;
            const uint32_t ad = st ? asU0 : asU1;
#pragma unroll
            for (int q = 0; q < 4; q++) cpasync16(ad + off + q * 16, sa + q * 4);
            CP_COMMIT();
        }

        const float* as = st ? As1 : As0;
        const float* bs = st ? Bs1 : Bs0;

        // fused latent norm on bx==0 CTAs (each thread owns 16 floats of its A row)
        if (bx == 0) {
            const float* ar = as + row * PT + half * 16;
            ulonglong2 q0 = *(const ulonglong2*)(ar);
            ulonglong2 q1 = *(const ulonglong2*)(ar + 4);
            ulonglong2 q2 = *(const ulonglong2*)(ar + 8);
            ulonglong2 q3 = *(const ulonglong2*)(ar + 12);
            ffma2(na2, q0.x, q0.x); ffma2(na2, q0.y, q0.y);
            ffma2(na2, q1.x, q1.x); ffma2(na2, q1.y, q1.y);
            ffma2(na2, q2.x, q2.x); ffma2(na2, q2.y, q2.y);
            ffma2(na2, q3.x, q3.x); ffma2(na2, q3.y, q3.y);
        }

        // main compute: k-pair packed FFMA2
#pragma unroll
        for (int k4 = 0; k4 < 8; k4++) {
            ulonglong2 a2[8];
#pragma unroll
            for (int i = 0; i < 8; i++)
                a2[i] = *(const ulonglong2*)(as + (ty + 16 * i) * PT + k4 * 4);
            ulonglong2 b2[4];
#pragma unroll
            for (int j = 0; j < 4; j++)
                b2[j] = *(const ulonglong2*)(bs + (tx + 16 * j) * PT + k4 * 4);
#pragma unroll
            for (int i = 0; i < 8; i++)
#pragma unroll
                for (int j = 0; j < 4; j++) ffma2(acc[i][j], a2[i].x, b2[j].x);
#pragma unroll
            for (int i = 0; i < 8; i++)
#pragma unroll
                for (int j = 0; j < 4; j++) ffma2(acc[i][j], a2[i].y, b2[j].y);
#pragma unroll
            for (int j = 0; j < 4; j++)
                b2[j] = *(const ulonglong2*)(bs + (tx + 16 * (j + 4)) * PT + k4 * 4);
#pragma unroll
            for (int i = 0; i < 8; i++)
#pragma unroll
                for (int j = 0; j < 4; j++) ffma2(acc[i][j + 4], a2[i].x, b2[j].x);
#pragma unroll
            for (int i = 0; i < 8; i++)
#pragma unroll
                for (int j = 0; j < 4; j++) ffma2(acc[i][j + 4], a2[i].y, b2[j].y);
        }

        // stage B(it+1) into buf st^1, drain A(it+1), one barrier
        if (more) {
            float* bsd = (st ? Bs0 : Bs1) + row * PT + half * 16;
#pragma unroll
            for (int q = 0; q < 4; q++) {
                ulonglong2 u = *(const ulonglong2*)&bv[q];
                ffma2(nb2, u.x, u.x); ffma2(nb2, u.y, u.y);
                *(float4*)(bsd + q * 4) = bv[q];
            }
            CP_WAIT0();
            __syncthreads();
        }
    }

    // norm writeout: thread pair (2r,2r+1) owns row r
    {
        float lo, hi;
        unpack2(nb2, lo, hi);
        float nb = lo + hi;
        nb += __shfl_xor_sync(0xFFFFFFFFu, nb, 1);
        if (half == 0) g_cnp[s][n0 + row] = nb;
        if (bx == 0) {
            unpack2(na2, lo, hi);
            float na = lo + hi;
            na += __shfl_xor_sync(0xFFFFFFFFu, na, 1);
            if (half == 0) g_lnp[s][row] = na;
        }
    }

    // result writeout: fold lo+hi (k-even / k-odd partial sums)
    float* op = g_part[s];
#pragma unroll
    for (int i = 0; i < 8; i++) {
        const int m = ty + 16 * i;
#pragma unroll
        for (int j = 0; j < 8; j++) {
            float lo, hi;
            unpack2(acc[i][j], lo, hi);
            op[(size_t)m * C_SZ + n0 + tx + 16 * j] = lo + hi;
        }
    }
}

// ---------------------------------------------------------------------------
// Per-row: reduce partials (+ inline norm sums) -> dist, top-5 (lowest-index
// tie-break), softmax, outputs, usage scatter-add, stash for quantize.
// ---------------------------------------------------------------------------
__global__ void topk_kernel(float* __restrict__ out) {
    const int b   = blockIdx.x;
    const int tid = threadIdx.x;

    __shared__ float sd[C_SZ];
    __shared__ float rv[256];
    __shared__ int   ri[256];
    __shared__ float topd[TOPK];
    __shared__ int   topi[TOPK];
    __shared__ float s_ln;

    if (tid == 0) {
        float v = 0.f;
#pragma unroll
        for (int s = 0; s < SPLITS; s++) v += g_lnp[s][b];
        s_ln = v;
    }
    __syncthreads();
    const float ln = s_ln;

    for (int c = tid; c < C_SZ; c += 256) {
        float dot = 0.f, cn = 0.f;
#pragma unroll
        for (int s = 0; s < SPLITS; s++) {
            dot += g_part[s][b * C_SZ + c];
            cn  += g_cnp[s][c];
        }
        float d2 = ln + cn - 2.f * dot;
        sd[c] = sqrtf(fmaxf(d2, 0.f));
    }
    __syncthreads();

    for (int k = 0; k < TOPK; k++) {
        float best = FLT_MAX;
        int   bi   = C_SZ;
        for (int c = tid; c < C_SZ; c += 256) {
            float d = sd[c];
            if (d < best || (d == best && c < bi)) { best = d; bi = c; }
        }
        rv[tid] = best; ri[tid] = bi;
        __syncthreads();
        for (int s = 128; s > 0; s >>= 1) {
            if (tid < s) {
                float o = rv[tid + s]; int oi = ri[tid + s];
                if (o < rv[tid] || (o == rv[tid] && oi < ri[tid])) {
                    rv[tid] = o; ri[tid] = oi;
                }
            }
            __syncthreads();
        }
        if (tid == 0) {
            topd[k] = rv[0];
            topi[k] = ri[0];
            sd[ri[0]] = FLT_MAX;
        }
        __syncthreads();
    }

    if (tid == 0) {
        float m0 = topd[0];
        float e[TOPK], ssum = 0.f;
#pragma unroll
        for (int k = 0; k < TOPK; k++) {
            e[k] = expf(-(topd[k] - m0) / TEMP);
            ssum += e[k];
        }
        float inv = 1.f / ssum;
        out[OFF_IDX  + b] = (float)topi[0];
        out[OFF_DIST + b] = topd[0];
#pragma unroll
        for (int k = 0; k < TOPK; k++) {
            float w = e[k] * inv;
            atomicAdd(&out[OFF_USAGE + topi[k]], w);
            g_topw[b][k] = w;
            g_topi[b][k] = topi[k];
        }
    }
}

// ---------------------------------------------------------------------------
// quantized[b] = sum_k w[b][k] * codebook[idx[b][k]]   grid (B, 16 chunks)
// ---------------------------------------------------------------------------
__global__ void quant_kernel(const float* __restrict__ codebook,
                             float* __restrict__ out) {
    const int b     = blockIdx.x;
    const int chunk = blockIdx.y;
    const int tid   = threadIdx.x;
    __shared__ int   si[TOPK];
    __shared__ float sw[TOPK];
    if (tid < TOPK) { si[tid] = g_topi[b][tid]; sw[tid] = g_topw[b][tid]; }
    __syncthreads();

    const float4* cb = (const float4*)codebook;
    float4* outq = (float4*)(out + OFF_Q) + (size_t)b * D4;

    const float4* r0 = cb + (size_t)si[0] * D4;
    const float4* r1 = cb + (size_t)si[1] * D4;
    const float4* r2 = cb + (size_t)si[2] * D4;
    const float4* r3 = cb + (size_t)si[3] * D4;
    const float4* r4 = cb + (size_t)si[4] * D4;
    const float w0 = sw[0], w1 = sw[1], w2 = sw[2], w3 = sw[3], w4 = sw[4];

    const int p0 = chunk * (D4 / 16);
    const int p1 = p0 + (D4 / 16);
    for (int p = p0 + tid; p < p1; p += 256) {
        float4 v0 = r0[p], v1 = r1[p], v2 = r2[p], v3 = r3[p], v4 = r4[p];
        float4 r;
        r.x = w0 * v0.x + w1 * v1.x + w2 * v2.x + w3 * v3.x + w4 * v4.x;
        r.y = w0 * v0.y + w1 * v1.y + w2 * v2.y + w3 * v3.y + w4 * v4.y;
        r.z = w0 * v0.z + w1 * v1.z + w2 * v2.z + w3 * v3.z + w4 * v4.z;
        r.w = w0 * v0.w + w1 * v1.w + w2 * v2.w + w3 * v3.w + w4 * v4.w;
        outq[p] = r;
    }
}

// ---------------------------------------------------------------------------
extern "C" void kernel_launch(void* const* d_in, const int* in_sizes, int n_in,
                              void* d_out, int out_size) {
    const float* latent   = (const float*)d_in[0];
    const float* codebook = (const float*)d_in[1];
    const float* usage    = (const float*)d_in[2];
    float* out = (float*)d_out;

    cudaFuncSetAttribute((const void*)gemm_kernel,
                         cudaFuncAttributeMaxDynamicSharedMemorySize, DYN_SMEM);
    gemm_kernel<<<dim3(NB, SPLITS), 256, DYN_SMEM>>>(latent, codebook,
                                                     usage, out + OFF_USAGE);
    topk_kernel<<<B_SZ, 256>>>(out);
    quant_kernel<<<dim3(B_SZ, 16), 256>>>(codebook, out);
}

// round 7
// speedup vs baseline: 1.0327x; 1.0096x over previous
#include <cuda_runtime.h>
#include <cstdint>
#include <math.h>
#include <float.h>

// Problem constants
#define B_SZ 128
#define C_SZ 1024
#define D_SZ 32000           // 8*250*16
#define D4   (D_SZ/4)
#define TOPK 5
#define TEMP 0.1f

// GEMM structure: K atoms of 32, split-K
#define BKA    32
#define SPLITS 18             // 8 * 18 = 144 CTAs = 1 wave
#define NB     8              // N tiles of 128

// smem: pitch 36 floats (144B rows: 16B-aligned, odd # of 16B granules -> conflict-free)
#define PT 36
#define FB_TILE_FLOATS (128 * PT)         // 4608 floats = 18432 B
#define DYN_SMEM (4 * FB_TILE_FLOATS * 4) // 73728 B

// Output layout (float32): quantized | main_indices | main_distances | usage_new
#define OFF_Q     0
#define OFF_IDX   (B_SZ * D_SZ)
#define OFF_DIST  (OFF_IDX + B_SZ)
#define OFF_USAGE (OFF_DIST + B_SZ)

// Scratch (device globals — no allocation allowed)
__device__ float g_part[SPLITS][B_SZ * C_SZ];   // 9.4 MB split-K partial dots
__device__ float g_cnp[SPLITS][C_SZ];           // codebook norm partials
__device__ float g_lnorm[B_SZ];
__device__ float g_topw[B_SZ][8];
__device__ int   g_topi[B_SZ][8];

// ---------------------------------------------------------------------------
// Helpers
// ---------------------------------------------------------------------------
__device__ __forceinline__ uint32_t smem_u32(const void* p) {
    uint32_t a;
    asm("{ .reg .u64 t; cvta.to.shared.u64 t, %1; cvt.u32.u64 %0, t; }" : "=r"(a) : "l"(p));
    return a;
}
__device__ __forceinline__ void unpack2(unsigned long long v, float& x, float& y) {
    asm("mov.b64 {%0, %1}, %2;" : "=f"(x), "=f"(y) : "l"(v));
}
__device__ __forceinline__ void ffma2(unsigned long long& d,
                                      unsigned long long a,
                                      unsigned long long b) {
    asm("fma.rn.f32x2 %0, %1, %2, %3;" : "=l"(d) : "l"(a), "l"(b), "l"(d));
}
__device__ __forceinline__ void cpasync16(uint32_t dst, const void* src) {
    asm volatile("cp.async.cg.shared.global [%0], [%1], 16;"
                 :: "r"(dst), "l"(src) : "memory");
}
#define CP_COMMIT() asm volatile("cp.async.commit_group;" ::: "memory")
#define CP_WAIT1()  asm volatile("cp.async.wait_group 1;" ::: "memory")

// ---------------------------------------------------------------------------
// Split-K GEMM (exact R4 structure — measured ~93us):
// FFMA2 k-pair inner loop, cp.async A (depth-1 double buffer),
// B via LDG->reg prefetch->STS with fused scalar codebook norm.
// grid = (NB, SPLITS), 256 threads.
// ---------------------------------------------------------------------------
__global__ __launch_bounds__(256, 1)
void gemm_kernel(const float* __restrict__ A,   // latent  [128][32000]
                 const float* __restrict__ Bm)  // codebook[1024][32000]
{
    extern __shared__ float dynf[];
    float* As0 = dynf;
    float* As1 = dynf + FB_TILE_FLOATS;
    float* Bs0 = dynf + 2 * FB_TILE_FLOATS;
    float* Bs1 = dynf + 3 * FB_TILE_FLOATS;

    const int t  = threadIdx.x;
    const int bx = blockIdx.x;
    const int s  = blockIdx.y;
    const int n0 = bx * 128;
    // uneven split: 1000 atoms = 18*55 + 10; splits 0..9 get 56
    const int tile0 = s * 55 + min(s, 10);
    const int ntile = 55 + (s < 10 ? 1 : 0);

    const int row  = t >> 1;
    const int half = t & 1;
    const int ty   = t >> 4;
    const int tx   = t & 15;

    const float* aSrc = A  + (size_t)row * D_SZ + half * 16;
    const float* bSrc = Bm + (size_t)(n0 + row) * D_SZ + half * 16;

    const uint32_t asU0 = smem_u32(As0);
    const uint32_t asU1 = smem_u32(As1);
    const uint32_t aOff = (uint32_t)(row * PT + half * 16) * 4u;

    unsigned long long acc[8][8];
#pragma unroll
    for (int i = 0; i < 8; i++)
#pragma unroll
        for (int j = 0; j < 8; j++) acc[i][j] = 0ULL;

    float nb = 0.f;
    float4 bv[4];

    // prologue: cp.async A(0); LDG B(0)
    {
        const float* src = aSrc + (size_t)tile0 * BKA;
#pragma unroll
        for (int q = 0; q < 4; q++) cpasync16(asU0 + aOff + q * 16, src + q * 4);
        CP_COMMIT();
        const float4* bp4 = (const float4*)(bSrc + (size_t)tile0 * BKA);
#pragma unroll
        for (int q = 0; q < 4; q++) bv[q] = bp4[q];
    }

    for (int it = 0; it < ntile; it++) {
        const int st = it & 1;
        // STS B(it) + fused codebook norm
        {
            float* bs = (st ? Bs1 : Bs0) + row * PT + half * 16;
#pragma unroll
            for (int q = 0; q < 4; q++) {
                float4 v = bv[q];
                nb += v.x * v.x + v.y * v.y + v.z * v.z + v.w * v.w;
                *(float4*)(bs + q * 4) = v;
            }
        }
        // issue cp.async A(it+1)
        if (it + 1 < ntile) {
            const float* src = aSrc + (size_t)(tile0 + it + 1) * BKA;
            uint32_t dstb = ((it + 1) & 1) ? asU1 : asU0;
#pragma unroll
            for (int q = 0; q < 4; q++) cpasync16(dstb + aOff + q * 16, src + q * 4);
        }
        CP_COMMIT();
        // LDG B(it+1)
        if (it + 1 < ntile) {
            const float4* bp4 = (const float4*)(bSrc + (size_t)(tile0 + it + 1) * BKA);
#pragma unroll
            for (int q = 0; q < 4; q++) bv[q] = bp4[q];
        }
        CP_WAIT1();
        __syncthreads();

        const float* as = st ? As1 : As0;
        const float* bs = st ? Bs1 : Bs0;
#pragma unroll
        for (int k4 = 0; k4 < 8; k4++) {
            ulonglong2 a2[8];
#pragma unroll
            for (int i = 0; i < 8; i++)
                a2[i] = *(const ulonglong2*)(as + (ty + 16 * i) * PT + k4 * 4);
            ulonglong2 b2[4];
#pragma unroll
            for (int j = 0; j < 4; j++)
                b2[j] = *(const ulonglong2*)(bs + (tx + 16 * j) * PT + k4 * 4);
#pragma unroll
            for (int i = 0; i < 8; i++)
#pragma unroll
                for (int j = 0; j < 4; j++) ffma2(acc[i][j], a2[i].x, b2[j].x);
#pragma unroll
            for (int i = 0; i < 8; i++)
#pragma unroll
                for (int j = 0; j < 4; j++) ffma2(acc[i][j], a2[i].y, b2[j].y);
#pragma unroll
            for (int j = 0; j < 4; j++)
                b2[j] = *(const ulonglong2*)(bs + (tx + 16 * (j + 4)) * PT + k4 * 4);
#pragma unroll
            for (int i = 0; i < 8; i++)
#pragma unroll
                for (int j = 0; j < 4; j++) ffma2(acc[i][j + 4], a2[i].x, b2[j].x);
#pragma unroll
            for (int i = 0; i < 8; i++)
#pragma unroll
                for (int j = 0; j < 4; j++) ffma2(acc[i][j + 4], a2[i].y, b2[j].y);
        }
        __syncthreads();
    }

    // codebook norm writeout: thread pair (2r,2r+1) owns row r
    nb += __shfl_xor_sync(0xFFFFFFFFu, nb, 1);
    if (half == 0) g_cnp[s][n0 + row] = nb;

    // result writeout: fold lo+hi (k-even / k-odd partial sums)
    float* op = g_part[s];
#pragma unroll
    for (int i = 0; i < 8; i++) {
        const int m = ty + 16 * i;
#pragma unroll
        for (int j = 0; j < 8; j++) {
            float lo, hi;
            unpack2(acc[i][j], lo, hi);
            op[(size_t)m * C_SZ + n0 + tx + 16 * j] = lo + hi;
        }
    }
}

// ---------------------------------------------------------------------------
// Latent row norms (16MB read) + usage copy. grid = 128 blocks.
// ---------------------------------------------------------------------------
__global__ void latent_norm_kernel(const float* __restrict__ latent,
                                   const float* __restrict__ usage_in,
                                   float* __restrict__ usage_out) {
    const int b   = blockIdx.x;
    const int tid = threadIdx.x;
    const float4* r = (const float4*)(latent + (size_t)b * D_SZ);
    float acc = 0.f;
    for (int i = tid; i < D4; i += 256) {
        float4 v = r[i];
        acc += v.x * v.x + v.y * v.y + v.z * v.z + v.w * v.w;
    }
    __shared__ float red[256];
    red[tid] = acc;
    __syncthreads();
    for (int s = 128; s > 0; s >>= 1) {
        if (tid < s) red[tid] += red[tid + s];
        __syncthreads();
    }
    if (tid == 0) g_lnorm[b] = red[0];
    if (b < 4) usage_out[b * 256 + tid] = usage_in[b * 256 + tid];
}

// ---------------------------------------------------------------------------
// Per-row: reduce partials (+ inline cnorm sum) -> dist, top-5 (lowest-index
// tie-break), softmax, outputs, usage scatter-add, stash for quantize.
// ---------------------------------------------------------------------------
__global__ void topk_kernel(float* __restrict__ out) {
    const int b   = blockIdx.x;
    const int tid = threadIdx.x;

    __shared__ float sd[C_SZ];
    __shared__ float rv[256];
    __shared__ int   ri[256];
    __shared__ float topd[TOPK];
    __shared__ int   topi[TOPK];

    const float ln = g_lnorm[b];
    for (int c = tid; c < C_SZ; c += 256) {
        float dot = 0.f, cn = 0.f;
#pragma unroll
        for (int s = 0; s < SPLITS; s++) {
            dot += g_part[s][b * C_SZ + c];
            cn  += g_cnp[s][c];
        }
        float d2 = ln + cn - 2.f * dot;
        sd[c] = sqrtf(fmaxf(d2, 0.f));
    }
    __syncthreads();

    for (int k = 0; k < TOPK; k++) {
        float best = FLT_MAX;
        int   bi   = C_SZ;
        for (int c = tid; c < C_SZ; c += 256) {
            float d = sd[c];
            if (d < best || (d == best && c < bi)) { best = d; bi = c; }
        }
        rv[tid] = best; ri[tid] = bi;
        __syncthreads();
        for (int s = 128; s > 0; s >>= 1) {
            if (tid < s) {
                float o = rv[tid + s]; int oi = ri[tid + s];
                if (o < rv[tid] || (o == rv[tid] && oi < ri[tid])) {
                    rv[tid] = o; ri[tid] = oi;
                }
            }
            __syncthreads();
        }
        if (tid == 0) {
            topd[k] = rv[0];
            topi[k] = ri[0];
            sd[ri[0]] = FLT_MAX;
        }
        __syncthreads();
    }

    if (tid == 0) {
        float m0 = topd[0];
        float e[TOPK], ssum = 0.f;
#pragma unroll
        for (int k = 0; k < TOPK; k++) {
            e[k] = expf(-(topd[k] - m0) / TEMP);
            ssum += e[k];
        }
        float inv = 1.f / ssum;
        out[OFF_IDX  + b] = (float)topi[0];
        out[OFF_DIST + b] = topd[0];
#pragma unroll
        for (int k = 0; k < TOPK; k++) {
            float w = e[k] * inv;
            atomicAdd(&out[OFF_USAGE + topi[k]], w);
            g_topw[b][k] = w;
            g_topi[b][k] = topi[k];
        }
    }
}

// ---------------------------------------------------------------------------
// quantized[b] = sum_k w[b][k] * codebook[idx[b][k]]   grid (B, 16 chunks)
// ---------------------------------------------------------------------------
__global__ void quant_kernel(const float* __restrict__ codebook,
                             float* __restrict__ out) {
    const int b     = blockIdx.x;
    const int chunk = blockIdx.y;
    const int tid   = threadIdx.x;
    __shared__ int   si[TOPK];
    __shared__ float sw[TOPK];
    if (tid < TOPK) { si[tid] = g_topi[b][tid]; sw[tid] = g_topw[b][tid]; }
    __syncthreads();

    const float4* cb = (const float4*)codebook;
    float4* outq = (float4*)(out + OFF_Q) + (size_t)b * D4;

    const float4* r0 = cb + (size_t)si[0] * D4;
    const float4* r1 = cb + (size_t)si[1] * D4;
    const float4* r2 = cb + (size_t)si[2] * D4;
    const float4* r3 = cb + (size_t)si[3] * D4;
    const float4* r4 = cb + (size_t)si[4] * D4;
    const float w0 = sw[0], w1 = sw[1], w2 = sw[2], w3 = sw[3], w4 = sw[4];

    const int p0 = chunk * (D4 / 16);
    const int p1 = p0 + (D4 / 16);
    for (int p = p0 + tid; p < p1; p += 256) {
        float4 v0 = r0[p], v1 = r1[p], v2 = r2[p], v3 = r3[p], v4 = r4[p];
        float4 r;
        r.x = w0 * v0.x + w1 * v1.x + w2 * v2.x + w3 * v3.x + w4 * v4.x;
        r.y = w0 * v0.y + w1 * v1.y + w2 * v2.y + w3 * v3.y + w4 * v4.y;
        r.z = w0 * v0.z + w1 * v1.z + w2 * v2.z + w3 * v3.z + w4 * v4.z;
        r.w = w0 * v0.w + w1 * v1.w + w2 * v2.w + w3 * v3.w + w4 * v4.w;
        outq[p] = r;
    }
}

// ---------------------------------------------------------------------------
extern "C" void kernel_launch(void* const* d_in, const int* in_sizes, int n_in,
                              void* d_out, int out_size) {
    const float* latent   = (const float*)d_in[0];
    const float* codebook = (const float*)d_in[1];
    const float* usage    = (const float*)d_in[2];
    float* out = (float*)d_out;

    cudaFuncSetAttribute((const void*)gemm_kernel,
                         cudaFuncAttributeMaxDynamicSharedMemorySize, DYN_SMEM);
    gemm_kernel<<<dim3(NB, SPLITS), 256, DYN_SMEM>>>(latent, codebook);
    latent_norm_kernel<<<B_SZ, 256>>>(latent, usage, out + OFF_USAGE);
    topk_kernel<<<B_SZ, 256>>>(out);
    quant_kernel<<<dim3(B_SZ, 16), 256>>>(codebook, out);
}

// round 8
// speedup vs baseline: 1.7291x; 1.6743x over previous
#include <cuda_runtime.h>
#include <cstdint>
#include <math.h>
#include <float.h>

// Problem constants
#define B_SZ 128
#define C_SZ 1024
#define D_SZ 32000           // 8*250*16
#define D4   (D_SZ/4)
#define TOPK 5
#define TEMP 0.1f

// GEMM structure: K atoms of 32 floats (128B rows), split-K
#define BKA    32
#define SPLITS 18             // 8 * 18 = 144 CTAs = 1 wave
#define NB     8              // N tiles of 128

// tensor path smem: per stage Ah|Al|Bh|Bl tiles of 128x128B
#define TILE_BYTES  16384
#define STAGE_BYTES (4 * TILE_BYTES)     // 65536
#define NSTAGE 3
// fallback smem: pitch 36 floats
#define PT 36
#define FB_TILE_FLOATS (128 * PT)
#define DYN_SMEM (NSTAGE * STAGE_BYTES + 1024)   // 197632 (covers fallback's 73728)

// idesc tf32: dtype=F32(1)<<4, atype=TF32(2)<<7, btype=TF32(2)<<10, N/8(16)<<17, M/16(8)<<24
#define MMA_IDESC 0x8200910u

// Output layout (float32): quantized | main_indices | main_distances | usage_new
#define OFF_Q     0
#define OFF_IDX   (B_SZ * D_SZ)
#define OFF_DIST  (OFF_IDX + B_SZ)
#define OFF_USAGE (OFF_DIST + B_SZ)

// Scratch (device globals — no allocation allowed)
__device__ float g_part[SPLITS][B_SZ * C_SZ];   // split-K partial dots
__device__ float g_cnp[SPLITS][C_SZ];           // codebook norm partials
__device__ float g_lnorm[B_SZ];
__device__ float g_topw[B_SZ][8];
__device__ int   g_topi[B_SZ][8];

// Feature gate: tcgen05 exists only in the sm_103a compilation pass.
#if defined(__CUDA_ARCH__) && defined(__CUDA_ARCH_FEAT_SM103_ALL)
#define HAS_TCGEN05 1
#else
#define HAS_TCGEN05 0
#endif

// ---------------------------------------------------------------------------
// Common helpers
// ---------------------------------------------------------------------------
__device__ __forceinline__ uint32_t smem_u32(const void* p) {
    uint32_t a;
    asm("{ .reg .u64 t; cvta.to.shared.u64 t, %1; cvt.u32.u64 %0, t; }" : "=r"(a) : "l"(p));
    return a;
}
__device__ __forceinline__ void unpack2(unsigned long long v, float& x, float& y) {
    asm("mov.b64 {%0, %1}, %2;" : "=f"(x), "=f"(y) : "l"(v));
}
__device__ __forceinline__ void ffma2(unsigned long long& d,
                                      unsigned long long a,
                                      unsigned long long b) {
    asm("fma.rn.f32x2 %0, %1, %2, %3;" : "=l"(d) : "l"(a), "l"(b), "l"(d));
}
__device__ __forceinline__ void cpasync16(uint32_t dst, const void* src) {
    asm volatile("cp.async.cg.shared.global [%0], [%1], 16;"
                 :: "r"(dst), "l"(src) : "memory");
}
#define CP_COMMIT() asm volatile("cp.async.commit_group;" ::: "memory")
#define CP_WAIT1()  asm volatile("cp.async.wait_group 1;" ::: "memory")

#if HAS_TCGEN05
// ---------------------------------------------------------------------------
// tcgen05 helpers (sm_103a pass only)
// ---------------------------------------------------------------------------
__device__ __forceinline__ bool elect1() {
    uint32_t p;
    asm volatile("{ .reg .pred p; elect.sync _|p, 0xFFFFFFFF; selp.b32 %0, 1, 0, p; }" : "=r"(p));
    return p != 0;
}
__device__ __forceinline__ void mbar_init(uint32_t mbar, uint32_t cnt) {
    asm volatile("mbarrier.init.shared.b64 [%0], %1;" :: "r"(mbar), "r"(cnt) : "memory");
}
__device__ __forceinline__ void mbar_wait(uint32_t mbar, uint32_t parity) {
    asm volatile("{\n\t.reg .pred P;\n\t"
                 "WL_%=:\n\t"
                 "mbarrier.try_wait.parity.acquire.cta.shared::cta.b64 P, [%0], %1, 0x989680;\n\t"
                 "@P bra.uni WD_%=;\n\t"
                 "bra.uni WL_%=;\n\t"
                 "WD_%=:\n\t}"
                 :: "r"(mbar), "r"(parity) : "memory");
}
__device__ __forceinline__ void tmem_alloc(uint32_t dst_smem, uint32_t ncols) {
    asm volatile("tcgen05.alloc.cta_group::1.sync.aligned.shared::cta.b32 [%0], %1;"
                 :: "r"(dst_smem), "r"(ncols) : "memory");
}
__device__ __forceinline__ void tmem_dealloc(uint32_t tmem, uint32_t ncols) {
    asm volatile("tcgen05.relinquish_alloc_permit.cta_group::1.sync.aligned;");
    asm volatile("tcgen05.dealloc.cta_group::1.sync.aligned.b32 %0, %1;" :: "r"(tmem), "r"(ncols));
}
__device__ __forceinline__ void mma_commit(uint32_t mbar) {
    asm volatile("tcgen05.commit.cta_group::1.mbarrier::arrive::one.shared::cluster.b64 [%0];"
                 :: "r"(mbar) : "memory");
}
__device__ __forceinline__ void mma_tf32_ss(uint32_t d, uint64_t ad, uint64_t bd, uint32_t en) {
    asm volatile("{\n\t.reg .pred p;\n\tsetp.ne.u32 p, %4, 0;\n\t"
                 "tcgen05.mma.cta_group::1.kind::tf32 [%0], %1, %2, %3, {%5, %5, %5, %5}, p;\n\t}"
                 :: "r"(d), "l"(ad), "l"(bd), "r"(MMA_IDESC), "r"(en), "r"(0u)
                 : "memory");
}
// SW128 K-major descriptor: layout=2(SW128), version=1, SBO=64, LBO=1
__device__ __forceinline__ uint64_t smem_desc(uint32_t addr) {
    return ((uint64_t)2 << 61) | ((uint64_t)1 << 46) | ((uint64_t)64 << 32) |
           ((uint64_t)1 << 16) | ((uint64_t)(addr >> 4) & 0x3FFF);
}
__device__ __forceinline__ uint32_t sw128(uint32_t off) { return off ^ ((off >> 3) & 0x70u); }

#define LDTM_X32(r, addr)                                                          \
    asm volatile("tcgen05.ld.sync.aligned.32x32b.x32.b32 "                         \
        "{%0, %1, %2, %3, %4, %5, %6, %7, %8, %9, %10, %11, %12, %13, %14, %15, "  \
        " %16, %17, %18, %19, %20, %21, %22, %23, %24, %25, %26, %27, %28, %29, %30, %31}, [%32];" \
        : "=r"((r)[0]), "=r"((r)[1]), "=r"((r)[2]), "=r"((r)[3]),                  \
          "=r"((r)[4]), "=r"((r)[5]), "=r"((r)[6]), "=r"((r)[7]),                  \
          "=r"((r)[8]), "=r"((r)[9]), "=r"((r)[10]), "=r"((r)[11]),                \
          "=r"((r)[12]), "=r"((r)[13]), "=r"((r)[14]), "=r"((r)[15]),              \
          "=r"((r)[16]), "=r"((r)[17]), "=r"((r)[18]), "=r"((r)[19]),              \
          "=r"((r)[20]), "=r"((r)[21]), "=r"((r)[22]), "=r"((r)[23]),              \
          "=r"((r)[24]), "=r"((r)[25]), "=r"((r)[26]), "=r"((r)[27]),              \
          "=r"((r)[28]), "=r"((r)[29]), "=r"((r)[30]), "=r"((r)[31])               \
        : "r"(addr))
#endif // HAS_TCGEN05

// ---------------------------------------------------------------------------
// GEMM: grid (NB, SPLITS), 256 threads.
// sm_103a pass: tcgen05 tf32 3-split, 3-stage ring, LDG prefetched a full tile.
// base pass (never selected at runtime): FFMA2 fallback.
// ---------------------------------------------------------------------------
__global__ __launch_bounds__(256, 1)
void gemm_kernel(const float* __restrict__ A,   // latent  [128][32000]
                 const float* __restrict__ Bm)  // codebook[1024][32000]
{
    extern __shared__ float dynf[];
    const int t  = threadIdx.x;
    const int bx = blockIdx.x;
    const int s  = blockIdx.y;
    const int n0 = bx * 128;
    // uneven split: 1000 atoms = 18*55 + 10; splits 0..9 get 56
    const int tile0 = s * 55 + min(s, 10);
    const int ntile = 55 + (s < 10 ? 1 : 0);

#if HAS_TCGEN05
    // ======================= tcgen05 tf32 path =============================
    __shared__ uint32_t s_tmem;
    __shared__ __align__(8) unsigned long long s_mbar[NSTAGE];
    const int wid  = t >> 5;
    const int lane = t & 31;

    char* bp = (char*)(((uintptr_t)dynf + 1023) & ~(uintptr_t)1023);
    const uint32_t base = smem_u32(bp);
    const uint32_t tmem_ptr_addr = smem_u32(&s_tmem);
    uint32_t mb[NSTAGE];
#pragma unroll
    for (int i = 0; i < NSTAGE; i++) mb[i] = smem_u32(&s_mbar[i]);

    if (wid == 0) tmem_alloc(tmem_ptr_addr, 128);
    if (t == 0) {
#pragma unroll
        for (int i = 0; i < NSTAGE; i++) mbar_init(mb[i], 1);
    }
    __syncthreads();
    uint32_t tmem;
    asm volatile("ld.shared.b32 %0, [%1];" : "=r"(tmem) : "r"(tmem_ptr_addr));

    const int rA = t >> 1;               // row 0..127
    const int cg = (t & 1) * 4;          // float4 group base
    const float* aRow = A  + (size_t)rA * D_SZ;
    const float* bRow = Bm + (size_t)(n0 + rA) * D_SZ;
    uint32_t stsOff[4];
#pragma unroll
    for (int j = 0; j < 4; j++)
        stsOff[j] = sw128((uint32_t)rA * 128u + (uint32_t)(cg + j) * 16u);

    float nb = 0.f;
    float4 av[4], bv[4];

    // prologue: LDG tile 0
    {
        const float4* a4 = (const float4*)(aRow + (size_t)tile0 * BKA);
        const float4* b4 = (const float4*)(bRow + (size_t)tile0 * BKA);
#pragma unroll
        for (int j = 0; j < 4; j++) { av[j] = a4[cg + j]; bv[j] = b4[cg + j]; }
    }

    for (int it = 0; it < ntile; it++) {
        const int stg = it % NSTAGE;

        // wait stage free: MMA of (it - NSTAGE) done
        if (it >= NSTAGE) mbar_wait(mb[stg], ((it - NSTAGE) / NSTAGE) & 1);

        // split hi/lo + STS (registers loaded last iteration)
        char* sb = bp + stg * STAGE_BYTES;
#pragma unroll
        for (int j = 0; j < 4; j++) {
            float4 v = av[j], h, l;
            h.x = __uint_as_float(__float_as_uint(v.x) & 0xFFFFE000u); l.x = v.x - h.x;
            h.y = __uint_as_float(__float_as_uint(v.y) & 0xFFFFE000u); l.y = v.y - h.y;
            h.z = __uint_as_float(__float_as_uint(v.z) & 0xFFFFE000u); l.z = v.z - h.z;
            h.w = __uint_as_float(__float_as_uint(v.w) & 0xFFFFE000u); l.w = v.w - h.w;
            *(float4*)(sb + 0 * TILE_BYTES + stsOff[j]) = h;
            *(float4*)(sb + 1 * TILE_BYTES + stsOff[j]) = l;
            float4 w = bv[j];
            nb += w.x * w.x + w.y * w.y + w.z * w.z + w.w * w.w;
            h.x = __uint_as_float(__float_as_uint(w.x) & 0xFFFFE000u); l.x = w.x - h.x;
            h.y = __uint_as_float(__float_as_uint(w.y) & 0xFFFFE000u); l.y = w.y - h.y;
            h.z = __uint_as_float(__float_as_uint(w.z) & 0xFFFFE000u); l.z = w.z - h.z;
            h.w = __uint_as_float(__float_as_uint(w.w) & 0xFFFFE000u); l.w = w.w - h.w;
            *(float4*)(sb + 2 * TILE_BYTES + stsOff[j]) = h;
            *(float4*)(sb + 3 * TILE_BYTES + stsOff[j]) = l;
        }
        __syncthreads();

        // MMA issue for this stage
        if (wid == 0 && elect1()) {
            asm volatile("fence.proxy.async.shared::cta;" ::: "memory");
            uint32_t sbu = base + stg * STAGE_BYTES;
            uint64_t dAh = smem_desc(sbu);
            uint64_t dAl = smem_desc(sbu + 1 * TILE_BYTES);
            uint64_t dBh = smem_desc(sbu + 2 * TILE_BYTES);
            uint64_t dBl = smem_desc(sbu + 3 * TILE_BYTES);
#pragma unroll
            for (int k = 0; k < 4; k++) mma_tf32_ss(tmem, dAh + 2 * k, dBh + 2 * k, (it > 0) || (k > 0));
#pragma unroll
            for (int k = 0; k < 4; k++) mma_tf32_ss(tmem, dAh + 2 * k, dBl + 2 * k, 1u);
#pragma unroll
            for (int k = 0; k < 4; k++) mma_tf32_ss(tmem, dAl + 2 * k, dBh + 2 * k, 1u);
            mma_commit(mb[stg]);
        }

        // LDG next tile — a full tile-time of latency cover
        if (it + 1 < ntile) {
            const float4* a4 = (const float4*)(aRow + (size_t)(tile0 + it + 1) * BKA);
            const float4* b4 = (const float4*)(bRow + (size_t)(tile0 + it + 1) * BKA);
#pragma unroll
            for (int j = 0; j < 4; j++) { av[j] = a4[cg + j]; bv[j] = b4[cg + j]; }
        }
    }

    // drain: tcgen05 ops complete in order -> wait for the last commit only
    mbar_wait(mb[(ntile - 1) % NSTAGE], ((ntile - 1) / NSTAGE) & 1);
    asm volatile("tcgen05.fence::after_thread_sync;" ::: "memory");

    // codebook norm writeout: thread pair (2r,2r+1) owns row r
    nb += __shfl_xor_sync(0xFFFFFFFFu, nb, 1);
    if ((t & 1) == 0) g_cnp[s][n0 + rA] = nb;

    // epilogue: TMEM -> g_part.  warps 0-3: cols 0-63, warps 4-7: cols 64-127
    {
        const int colb = (wid >> 2) * 64;
        const int m = (wid & 3) * 32 + lane;
        float* dst = &g_part[s][(size_t)m * C_SZ + n0 + colb];
        uint32_t dr[32];
        LDTM_X32(dr, tmem + colb);
        asm volatile("tcgen05.wait::ld.sync.aligned;" ::: "memory");
#pragma unroll
        for (int j = 0; j < 8; j++)
            ((float4*)dst)[j] = make_float4(__uint_as_float(dr[4 * j + 0]), __uint_as_float(dr[4 * j + 1]),
                                            __uint_as_float(dr[4 * j + 2]), __uint_as_float(dr[4 * j + 3]));
        LDTM_X32(dr, tmem + colb + 32);
        asm volatile("tcgen05.wait::ld.sync.aligned;" ::: "memory");
#pragma unroll
        for (int j = 0; j < 8; j++)
            ((float4*)(dst + 32))[j] = make_float4(__uint_as_float(dr[4 * j + 0]), __uint_as_float(dr[4 * j + 1]),
                                                   __uint_as_float(dr[4 * j + 2]), __uint_as_float(dr[4 * j + 3]));
    }
    __syncthreads();
    if (wid == 0) tmem_dealloc(tmem, 128);

#else
    // ================= FFMA2 fallback (base pass; not selected at runtime) ==
    float* As0 = dynf;
    float* As1 = dynf + FB_TILE_FLOATS;
    float* Bs0 = dynf + 2 * FB_TILE_FLOATS;
    float* Bs1 = dynf + 3 * FB_TILE_FLOATS;

    const int row  = t >> 1;
    const int half = t & 1;
    const int ty   = t >> 4;
    const int tx   = t & 15;

    const float* aSrc = A  + (size_t)row * D_SZ + half * 16;
    const float* bSrc = Bm + (size_t)(n0 + row) * D_SZ + half * 16;

    const uint32_t asU0 = smem_u32(As0);
    const uint32_t asU1 = smem_u32(As1);
    const uint32_t aOff = (uint32_t)(row * PT + half * 16) * 4u;

    unsigned long long acc[8][8];
#pragma unroll
    for (int i = 0; i < 8; i++)
#pragma unroll
        for (int j = 0; j < 8; j++) acc[i][j] = 0ULL;

    float nb = 0.f;
    float4 bv[4];

    {
        const float* src = aSrc + (size_t)tile0 * BKA;
#pragma unroll
        for (int q = 0; q < 4; q++) cpasync16(asU0 + aOff + q * 16, src + q * 4);
        CP_COMMIT();
        const float4* bp4 = (const float4*)(bSrc + (size_t)tile0 * BKA);
#pragma unroll
        for (int q = 0; q < 4; q++) bv[q] = bp4[q];
    }

    for (int it = 0; it < ntile; it++) {
        const int st = it & 1;
        {
            float* bs = (st ? Bs1 : Bs0) + row * PT + half * 16;
#pragma unroll
            for (int q = 0; q < 4; q++) {
                float4 v = bv[q];
                nb += v.x * v.x + v.y * v.y + v.z * v.z + v.w * v.w;
                *(float4*)(bs + q * 4) = v;
            }
        }
        if (it + 1 < ntile) {
            const float* src = aSrc + (size_t)(tile0 + it + 1) * BKA;
            uint32_t dstb = ((it + 1) & 1) ? asU1 : asU0;
#pragma unroll
            for (int q = 0; q < 4; q++) cpasync16(dstb + aOff + q * 16, src + q * 4);
        }
        CP_COMMIT();
        if (it + 1 < ntile) {
            const float4* bp4 = (const float4*)(bSrc + (size_t)(tile0 + it + 1) * BKA);
#pragma unroll
            for (int q = 0; q < 4; q++) bv[q] = bp4[q];
        }
        CP_WAIT1();
        __syncthreads();

        const float* as = st ? As1 : As0;
        const float* bs = st ? Bs1 : Bs0;
#pragma unroll
        for (int k4 = 0; k4 < 8; k4++) {
            ulonglong2 a2[8];
#pragma unroll
            for (int i = 0; i < 8; i++)
                a2[i] = *(const ulonglong2*)(as + (ty + 16 * i) * PT + k4 * 4);
            ulonglong2 b2[4];
#pragma unroll
            for (int j = 0; j < 4; j++)
                b2[j] = *(const ulonglong2*)(bs + (tx + 16 * j) * PT + k4 * 4);
#pragma unroll
            for (int i = 0; i < 8; i++)
#pragma unroll
                for (int j = 0; j < 4; j++) ffma2(acc[i][j], a2[i].x, b2[j].x);
#pragma unroll
            for (int i = 0; i < 8; i++)
#pragma unroll
                for (int j = 0; j < 4; j++) ffma2(acc[i][j], a2[i].y, b2[j].y);
#pragma unroll
            for (int j = 0; j < 4; j++)
                b2[j] = *(const ulonglong2*)(bs + (tx + 16 * (j + 4)) * PT + k4 * 4);
#pragma unroll
            for (int i = 0; i < 8; i++)
#pragma unroll
                for (int j = 0; j < 4; j++) ffma2(acc[i][j + 4], a2[i].x, b2[j].x);
#pragma unroll
            for (int i = 0; i < 8; i++)
#pragma unroll
                for (int j = 0; j < 4; j++) ffma2(acc[i][j + 4], a2[i].y, b2[j].y);
        }
        __syncthreads();
    }

    nb += __shfl_xor_sync(0xFFFFFFFFu, nb, 1);
    if (half == 0) g_cnp[s][n0 + row] = nb;

    float* op = g_part[s];
#pragma unroll
    for (int i = 0; i < 8; i++) {
        const int m = ty + 16 * i;
#pragma unroll
        for (int j = 0; j < 8; j++) {
            float lo, hi;
            unpack2(acc[i][j], lo, hi);
            op[(size_t)m * C_SZ + n0 + tx + 16 * j] = lo + hi;
        }
    }
#endif
}

// ---------------------------------------------------------------------------
// Latent row norms + usage copy. grid = 128 blocks.
// ---------------------------------------------------------------------------
__global__ void latent_norm_kernel(const float* __restrict__ latent,
                                   const float* __restrict__ usage_in,
                                   float* __restrict__ usage_out) {
    const int b   = blockIdx.x;
    const int tid = threadIdx.x;
    const float4* r = (const float4*)(latent + (size_t)b * D_SZ);
    float acc = 0.f;
    for (int i = tid; i < D4; i += 256) {
        float4 v = r[i];
        acc += v.x * v.x + v.y * v.y + v.z * v.z + v.w * v.w;
    }
    __shared__ float red[256];
    red[tid] = acc;
    __syncthreads();
    for (int s = 128; s > 0; s >>= 1) {
        if (tid < s) red[tid] += red[tid + s];
        __syncthreads();
    }
    if (tid == 0) g_lnorm[b] = red[0];
    if (b < 4) usage_out[b * 256 + tid] = usage_in[b * 256 + tid];
}

// ---------------------------------------------------------------------------
// Per-row: reduce partials (+ inline cnorm sum) -> dist, top-5 (lowest-index
// tie-break), softmax, outputs, usage scatter-add, stash for quantize.
// ---------------------------------------------------------------------------
__global__ void topk_kernel(float* __restrict__ out) {
    const int b   = blockIdx.x;
    const int tid = threadIdx.x;

    __shared__ float sd[C_SZ];
    __shared__ float rv[256];
    __shared__ int   ri[256];
    __shared__ float topd[TOPK];
    __shared__ int   topi[TOPK];

    const float ln = g_lnorm[b];
    for (int c = tid; c < C_SZ; c += 256) {
        float dot = 0.f, cn = 0.f;
#pragma unroll
        for (int s = 0; s < SPLITS; s++) {
            dot += g_part[s][b * C_SZ + c];
            cn  += g_cnp[s][c];
        }
        float d2 = ln + cn - 2.f * dot;
        sd[c] = sqrtf(fmaxf(d2, 0.f));
    }
    __syncthreads();

    for (int k = 0; k < TOPK; k++) {
        float best = FLT_MAX;
        int   bi   = C_SZ;
        for (int c = tid; c < C_SZ; c += 256) {
            float d = sd[c];
            if (d < best || (d == best && c < bi)) { best = d; bi = c; }
        }
        rv[tid] = best; ri[tid] = bi;
        __syncthreads();
        for (int s = 128; s > 0; s >>= 1) {
            if (tid < s) {
                float o = rv[tid + s]; int oi = ri[tid + s];
                if (o < rv[tid] || (o == rv[tid] && oi < ri[tid])) {
                    rv[tid] = o; ri[tid] = oi;
                }
            }
            __syncthreads();
        }
        if (tid == 0) {
            topd[k] = rv[0];
            topi[k] = ri[0];
            sd[ri[0]] = FLT_MAX;
        }
        __syncthreads();
    }

    if (tid == 0) {
        float m0 = topd[0];
        float e[TOPK], ssum = 0.f;
#pragma unroll
        for (int k = 0; k < TOPK; k++) {
            e[k] = expf(-(topd[k] - m0) / TEMP);
            ssum += e[k];
        }
        float inv = 1.f / ssum;
        out[OFF_IDX  + b] = (float)topi[0];
        out[OFF_DIST + b] = topd[0];
#pragma unroll
        for (int k = 0; k < TOPK; k++) {
            float w = e[k] * inv;
            atomicAdd(&out[OFF_USAGE + topi[k]], w);
            g_topw[b][k] = w;
            g_topi[b][k] = topi[k];
        }
    }
}

// ---------------------------------------------------------------------------
// quantized[b] = sum_k w[b][k] * codebook[idx[b][k]]   grid (B, 16 chunks)
// ---------------------------------------------------------------------------
__global__ void quant_kernel(const float* __restrict__ codebook,
                             float* __restrict__ out) {
    const int b     = blockIdx.x;
    const int chunk = blockIdx.y;
    const int tid   = threadIdx.x;
    __shared__ int   si[TOPK];
    __shared__ float sw[TOPK];
    if (tid < TOPK) { si[tid] = g_topi[b][tid]; sw[tid] = g_topw[b][tid]; }
    __syncthreads();

    const float4* cb = (const float4*)codebook;
    float4* outq = (float4*)(out + OFF_Q) + (size_t)b * D4;

    const float4* r0 = cb + (size_t)si[0] * D4;
    const float4* r1 = cb + (size_t)si[1] * D4;
    const float4* r2 = cb + (size_t)si[2] * D4;
    const float4* r3 = cb + (size_t)si[3] * D4;
    const float4* r4 = cb + (size_t)si[4] * D4;
    const float w0 = sw[0], w1 = sw[1], w2 = sw[2], w3 = sw[3], w4 = sw[4];

    const int p0 = chunk * (D4 / 16);
    const int p1 = p0 + (D4 / 16);
    for (int p = p0 + tid; p < p1; p += 256) {
        float4 v0 = r0[p], v1 = r1[p], v2 = r2[p], v3 = r3[p], v4 = r4[p];
        float4 r;
        r.x = w0 * v0.x + w1 * v1.x + w2 * v2.x + w3 * v3.x + w4 * v4.x;
        r.y = w0 * v0.y + w1 * v1.y + w2 * v2.y + w3 * v3.y + w4 * v4.y;
        r.z = w0 * v0.z + w1 * v1.z + w2 * v2.z + w3 * v3.z + w4 * v4.z;
        r.w = w0 * v0.w + w1 * v1.w + w2 * v2.w + w3 * v3.w + w4 * v4.w;
        outq[p] = r;
    }
}

// ---------------------------------------------------------------------------
extern "C" void kernel_launch(void* const* d_in, const int* in_sizes, int n_in,
                              void* d_out, int out_size) {
    const float* latent   = (const float*)d_in[0];
    const float* codebook = (const float*)d_in[1];
    const float* usage    = (const float*)d_in[2];
    float* out = (float*)d_out;

    cudaFuncSetAttribute((const void*)gemm_kernel,
                         cudaFuncAttributeMaxDynamicSharedMemorySize, DYN_SMEM);
    gemm_kernel<<<dim3(NB, SPLITS), 256, DYN_SMEM>>>(latent, codebook);
    latent_norm_kernel<<<B_SZ, 256>>>(latent, usage, out + OFF_USAGE);
    topk_kernel<<<B_SZ, 256>>>(out);
    quant_kernel<<<dim3(B_SZ, 16), 256>>>(codebook, out);
}

// round 9
// speedup vs baseline: 1.9263x; 1.1141x over previous
#include <cuda_runtime.h>
#include <cstdint>
#include <math.h>
#include <float.h>

// Problem constants
#define B_SZ 128
#define C_SZ 1024
#define D_SZ 32000           // 8*250*16
#define D4   (D_SZ/4)
#define TOPK 5
#define TEMP 0.1f

// GEMM structure: K atoms of 32 floats (128B rows), split-K
#define BKA    32
#define SPLITS 18             // 8 * 18 = 144 CTAs = 1 wave
#define NB     8              // N tiles of 128

// tensor path smem: per stage Ah|Al|Bh|Bl tiles of 128x128B
#define TILE_BYTES  16384
#define STAGE_BYTES (4 * TILE_BYTES)     // 65536
#define NSTAGE 3
// fallback smem: pitch 36 floats
#define PT 36
#define FB_TILE_FLOATS (128 * PT)
#define DYN_SMEM (NSTAGE * STAGE_BYTES + 1024)   // 197632

// idesc tf32: dtype=F32(1)<<4, atype=TF32(2)<<7, btype=TF32(2)<<10, N/8(16)<<17, M/16(8)<<24
#define MMA_IDESC 0x8200910u

// Output layout (float32): quantized | main_indices | main_distances | usage_new
#define OFF_Q     0
#define OFF_IDX   (B_SZ * D_SZ)
#define OFF_DIST  (OFF_IDX + B_SZ)
#define OFF_USAGE (OFF_DIST + B_SZ)

// Scratch (device globals — no allocation allowed)
__device__ float g_part[SPLITS][B_SZ * C_SZ];   // split-K partial dots
__device__ float g_cnp[SPLITS][C_SZ];           // codebook norm partials
__device__ float g_lnp[SPLITS][B_SZ];           // latent norm partials
__device__ float g_topw[B_SZ][8];
__device__ int   g_topi[B_SZ][8];

// Feature gate: tcgen05 exists only in the sm_103a compilation pass.
#if defined(__CUDA_ARCH__) && defined(__CUDA_ARCH_FEAT_SM103_ALL)
#define HAS_TCGEN05 1
#else
#define HAS_TCGEN05 0
#endif

// ---------------------------------------------------------------------------
// Common helpers
// ---------------------------------------------------------------------------
__device__ __forceinline__ uint32_t smem_u32(const void* p) {
    uint32_t a;
    asm("{ .reg .u64 t; cvta.to.shared.u64 t, %1; cvt.u32.u64 %0, t; }" : "=r"(a) : "l"(p));
    return a;
}
__device__ __forceinline__ void unpack2(unsigned long long v, float& x, float& y) {
    asm("mov.b64 {%0, %1}, %2;" : "=f"(x), "=f"(y) : "l"(v));
}
__device__ __forceinline__ void ffma2(unsigned long long& d,
                                      unsigned long long a,
                                      unsigned long long b) {
    asm("fma.rn.f32x2 %0, %1, %2, %3;" : "=l"(d) : "l"(a), "l"(b), "l"(d));
}
__device__ __forceinline__ void cpasync16(uint32_t dst, const void* src) {
    asm volatile("cp.async.cg.shared.global [%0], [%1], 16;"
                 :: "r"(dst), "l"(src) : "memory");
}
#define CP_COMMIT() asm volatile("cp.async.commit_group;" ::: "memory")
#define CP_WAIT1()  asm volatile("cp.async.wait_group 1;" ::: "memory")

#if HAS_TCGEN05
// ---------------------------------------------------------------------------
// tcgen05 helpers (sm_103a pass only)
// ---------------------------------------------------------------------------
__device__ __forceinline__ bool elect1() {
    uint32_t p;
    asm volatile("{ .reg .pred p; elect.sync _|p, 0xFFFFFFFF; selp.b32 %0, 1, 0, p; }" : "=r"(p));
    return p != 0;
}
__device__ __forceinline__ void mbar_init(uint32_t mbar, uint32_t cnt) {
    asm volatile("mbarrier.init.shared.b64 [%0], %1;" :: "r"(mbar), "r"(cnt) : "memory");
}
__device__ __forceinline__ void mbar_wait(uint32_t mbar, uint32_t parity) {
    asm volatile("{\n\t.reg .pred P;\n\t"
                 "WL_%=:\n\t"
                 "mbarrier.try_wait.parity.acquire.cta.shared::cta.b64 P, [%0], %1, 0x989680;\n\t"
                 "@P bra.uni WD_%=;\n\t"
                 "bra.uni WL_%=;\n\t"
                 "WD_%=:\n\t}"
                 :: "r"(mbar), "r"(parity) : "memory");
}
__device__ __forceinline__ void tmem_alloc(uint32_t dst_smem, uint32_t ncols) {
    asm volatile("tcgen05.alloc.cta_group::1.sync.aligned.shared::cta.b32 [%0], %1;"
                 :: "r"(dst_smem), "r"(ncols) : "memory");
}
__device__ __forceinline__ void tmem_dealloc(uint32_t tmem, uint32_t ncols) {
    asm volatile("tcgen05.relinquish_alloc_permit.cta_group::1.sync.aligned;");
    asm volatile("tcgen05.dealloc.cta_group::1.sync.aligned.b32 %0, %1;" :: "r"(tmem), "r"(ncols));
}
__device__ __forceinline__ void mma_commit(uint32_t mbar) {
    asm volatile("tcgen05.commit.cta_group::1.mbarrier::arrive::one.shared::cluster.b64 [%0];"
                 :: "r"(mbar) : "memory");
}
__device__ __forceinline__ void mma_tf32_ss(uint32_t d, uint64_t ad, uint64_t bd, uint32_t en) {
    asm volatile("{\n\t.reg .pred p;\n\tsetp.ne.u32 p, %4, 0;\n\t"
                 "tcgen05.mma.cta_group::1.kind::tf32 [%0], %1, %2, %3, {%5, %5, %5, %5}, p;\n\t}"
                 :: "r"(d), "l"(ad), "l"(bd), "r"(MMA_IDESC), "r"(en), "r"(0u)
                 : "memory");
}
// SW128 K-major descriptor: layout=2(SW128), version=1, SBO=64, LBO=1
__device__ __forceinline__ uint64_t smem_desc(uint32_t addr) {
    return ((uint64_t)2 << 61) | ((uint64_t)1 << 46) | ((uint64_t)64 << 32) |
           ((uint64_t)1 << 16) | ((uint64_t)(addr >> 4) & 0x3FFF);
}
__device__ __forceinline__ uint32_t sw128(uint32_t off) { return off ^ ((off >> 3) & 0x70u); }

#define LDTM_X32(r, addr)                                                          \
    asm volatile("tcgen05.ld.sync.aligned.32x32b.x32.b32 "                         \
        "{%0, %1, %2, %3, %4, %5, %6, %7, %8, %9, %10, %11, %12, %13, %14, %15, "  \
        " %16, %17, %18, %19, %20, %21, %22, %23, %24, %25, %26, %27, %28, %29, %30, %31}, [%32];" \
        : "=r"((r)[0]), "=r"((r)[1]), "=r"((r)[2]), "=r"((r)[3]),                  \
          "=r"((r)[4]), "=r"((r)[5]), "=r"((r)[6]), "=r"((r)[7]),                  \
          "=r"((r)[8]), "=r"((r)[9]), "=r"((r)[10]), "=r"((r)[11]),                \
          "=r"((r)[12]), "=r"((r)[13]), "=r"((r)[14]), "=r"((r)[15]),              \
          "=r"((r)[16]), "=r"((r)[17]), "=r"((r)[18]), "=r"((r)[19]),              \
          "=r"((r)[20]), "=r"((r)[21]), "=r"((r)[22]), "=r"((r)[23]),              \
          "=r"((r)[24]), "=r"((r)[25]), "=r"((r)[26]), "=r"((r)[27]),              \
          "=r"((r)[28]), "=r"((r)[29]), "=r"((r)[30]), "=r"((r)[31])               \
        : "r"(addr))
#endif // HAS_TCGEN05

// ---------------------------------------------------------------------------
// GEMM: grid (NB, SPLITS), 256 threads.
// sm_103a pass: tcgen05 tf32 (3xTF32 correction), 3-stage ring,
//   R4 producer ordering (LDG at loop top, BEFORE the mbar wait).
// base pass (never selected at runtime): FFMA2 fallback.
// ---------------------------------------------------------------------------
__global__ __launch_bounds__(256, 1)
void gemm_kernel(const float* __restrict__ A,   // latent  [128][32000]
                 const float* __restrict__ Bm,  // codebook[1024][32000]
                 const float* __restrict__ usage_in,
                 float* __restrict__ usage_out)
{
    extern __shared__ float dynf[];
    const int t  = threadIdx.x;
    const int bx = blockIdx.x;
    const int s  = blockIdx.y;
    const int n0 = bx * 128;
    // uneven split: 1000 atoms = 18*55 + 10; splits 0..9 get 56
    const int tile0 = s * 55 + min(s, 10);
    const int ntile = 55 + (s < 10 ? 1 : 0);

    // usage copy (ordered before topk's atomics by stream order)
    if (bx == 0 && s == 0)
        ((float4*)usage_out)[t] = ((const float4*)usage_in)[t];

#if HAS_TCGEN05
    // ======================= tcgen05 tf32 path =============================
    __shared__ uint32_t s_tmem;
    __shared__ __align__(8) unsigned long long s_mbar[NSTAGE];
    const int wid  = t >> 5;
    const int lane = t & 31;

    char* bp = (char*)(((uintptr_t)dynf + 1023) & ~(uintptr_t)1023);
    const uint32_t base = smem_u32(bp);
    const uint32_t tmem_ptr_addr = smem_u32(&s_tmem);
    uint32_t mb[NSTAGE];
#pragma unroll
    for (int i = 0; i < NSTAGE; i++) mb[i] = smem_u32(&s_mbar[i]);

    if (wid == 0) tmem_alloc(tmem_ptr_addr, 128);
    if (t == 0) {
#pragma unroll
        for (int i = 0; i < NSTAGE; i++) mbar_init(mb[i], 1);
    }
    __syncthreads();
    uint32_t tmem;
    asm volatile("ld.shared.b32 %0, [%1];" : "=r"(tmem) : "r"(tmem_ptr_addr));

    const int rA = t >> 1;               // row 0..127
    const int cg = (t & 1) * 4;          // float4 group base
    const float* aRow = A  + (size_t)rA * D_SZ;
    const float* bRow = Bm + (size_t)(n0 + rA) * D_SZ;
    uint32_t stsOff[4];
#pragma unroll
    for (int j = 0; j < 4; j++)
        stsOff[j] = sw128((uint32_t)rA * 128u + (uint32_t)(cg + j) * 16u);

    float nb = 0.f, na = 0.f;

    for (int it = 0; it < ntile; it++) {
        const int stg = it % NSTAGE;
        const int k0 = (tile0 + it) * BKA;

        // LDG tile it FIRST — the mbar wait below hides this latency
        float4 av[4], bv[4];
        const float4* a4 = (const float4*)(aRow + k0);
        const float4* b4 = (const float4*)(bRow + k0);
#pragma unroll
        for (int j = 0; j < 4; j++) { av[j] = a4[cg + j]; bv[j] = b4[cg + j]; }

        // wait stage free: MMA of (it - NSTAGE) done
        if (it >= NSTAGE) mbar_wait(mb[stg], ((it - NSTAGE) / NSTAGE) & 1);

        // fused norms from the just-loaded registers
        char* sb = bp + stg * STAGE_BYTES;
#pragma unroll
        for (int j = 0; j < 4; j++) {
            float4 v = av[j], h, l;
            if (bx == 0) na += v.x * v.x + v.y * v.y + v.z * v.z + v.w * v.w;
            h.x = __uint_as_float(__float_as_uint(v.x) & 0xFFFFE000u); l.x = v.x - h.x;
            h.y = __uint_as_float(__float_as_uint(v.y) & 0xFFFFE000u); l.y = v.y - h.y;
            h.z = __uint_as_float(__float_as_uint(v.z) & 0xFFFFE000u); l.z = v.z - h.z;
            h.w = __uint_as_float(__float_as_uint(v.w) & 0xFFFFE000u); l.w = v.w - h.w;
            *(float4*)(sb + 0 * TILE_BYTES + stsOff[j]) = h;
            *(float4*)(sb + 1 * TILE_BYTES + stsOff[j]) = l;
            float4 w = bv[j];
            nb += w.x * w.x + w.y * w.y + w.z * w.z + w.w * w.w;
            h.x = __uint_as_float(__float_as_uint(w.x) & 0xFFFFE000u); l.x = w.x - h.x;
            h.y = __uint_as_float(__float_as_uint(w.y) & 0xFFFFE000u); l.y = w.y - h.y;
            h.z = __uint_as_float(__float_as_uint(w.z) & 0xFFFFE000u); l.z = w.z - h.z;
            h.w = __uint_as_float(__float_as_uint(w.w) & 0xFFFFE000u); l.w = w.w - h.w;
            *(float4*)(sb + 2 * TILE_BYTES + stsOff[j]) = h;
            *(float4*)(sb + 3 * TILE_BYTES + stsOff[j]) = l;
        }
        __syncthreads();

        // MMA issue for this stage
        if (wid == 0 && elect1()) {
            asm volatile("fence.proxy.async.shared::cta;" ::: "memory");
            uint32_t sbu = base + stg * STAGE_BYTES;
            uint64_t dAh = smem_desc(sbu);
            uint64_t dAl = smem_desc(sbu + 1 * TILE_BYTES);
            uint64_t dBh = smem_desc(sbu + 2 * TILE_BYTES);
            uint64_t dBl = smem_desc(sbu + 3 * TILE_BYTES);
#pragma unroll
            for (int k = 0; k < 4; k++) mma_tf32_ss(tmem, dAh + 2 * k, dBh + 2 * k, (it > 0) || (k > 0));
#pragma unroll
            for (int k = 0; k < 4; k++) mma_tf32_ss(tmem, dAh + 2 * k, dBl + 2 * k, 1u);
#pragma unroll
            for (int k = 0; k < 4; k++) mma_tf32_ss(tmem, dAl + 2 * k, dBh + 2 * k, 1u);
            mma_commit(mb[stg]);
        }
    }

    // drain: tcgen05 ops complete in order -> wait for the last commit only
    mbar_wait(mb[(ntile - 1) % NSTAGE], ((ntile - 1) / NSTAGE) & 1);
    asm volatile("tcgen05.fence::after_thread_sync;" ::: "memory");

    // norm writeout: thread pair (2r,2r+1) owns row r
    nb += __shfl_xor_sync(0xFFFFFFFFu, nb, 1);
    if ((t & 1) == 0) g_cnp[s][n0 + rA] = nb;
    if (bx == 0) {
        na += __shfl_xor_sync(0xFFFFFFFFu, na, 1);
        if ((t & 1) == 0) g_lnp[s][rA] = na;
    }

    // epilogue: TMEM -> g_part.  warps 0-3: cols 0-63, warps 4-7: cols 64-127
    {
        const int colb = (wid >> 2) * 64;
        const int m = (wid & 3) * 32 + lane;
        float* dst = &g_part[s][(size_t)m * C_SZ + n0 + colb];
        uint32_t dr[32];
        LDTM_X32(dr, tmem + colb);
        asm volatile("tcgen05.wait::ld.sync.aligned;" ::: "memory");
#pragma unroll
        for (int j = 0; j < 8; j++)
            ((float4*)dst)[j] = make_float4(__uint_as_float(dr[4 * j + 0]), __uint_as_float(dr[4 * j + 1]),
                                            __uint_as_float(dr[4 * j + 2]), __uint_as_float(dr[4 * j + 3]));
        LDTM_X32(dr, tmem + colb + 32);
        asm volatile("tcgen05.wait::ld.sync.aligned;" ::: "memory");
#pragma unroll
        for (int j = 0; j < 8; j++)
            ((float4*)(dst + 32))[j] = make_float4(__uint_as_float(dr[4 * j + 0]), __uint_as_float(dr[4 * j + 1]),
                                                   __uint_as_float(dr[4 * j + 2]), __uint_as_float(dr[4 * j + 3]));
    }
    __syncthreads();
    if (wid == 0) tmem_dealloc(tmem, 128);

#else
    // ================= FFMA2 fallback (base pass; not selected at runtime) ==
    float* As0 = dynf;
    float* As1 = dynf + FB_TILE_FLOATS;
    float* Bs0 = dynf + 2 * FB_TILE_FLOATS;
    float* Bs1 = dynf + 3 * FB_TILE_FLOATS;

    const int row  = t >> 1;
    const int half = t & 1;
    const int ty   = t >> 4;
    const int tx   = t & 15;

    const float* aSrc = A  + (size_t)row * D_SZ + half * 16;
    const float* bSrc = Bm + (size_t)(n0 + row) * D_SZ + half * 16;

    const uint32_t asU0 = smem_u32(As0);
    const uint32_t asU1 = smem_u32(As1);
    const uint32_t aOff = (uint32_t)(row * PT + half * 16) * 4u;

    unsigned long long acc[8][8];
#pragma unroll
    for (int i = 0; i < 8; i++)
#pragma unroll
        for (int j = 0; j < 8; j++) acc[i][j] = 0ULL;

    float nb = 0.f, na = 0.f;
    float4 bv[4];

    {
        const float* src = aSrc + (size_t)tile0 * BKA;
#pragma unroll
        for (int q = 0; q < 4; q++) cpasync16(asU0 + aOff + q * 16, src + q * 4);
        CP_COMMIT();
        const float4* bp4 = (const float4*)(bSrc + (size_t)tile0 * BKA);
#pragma unroll
        for (int q = 0; q < 4; q++) bv[q] = bp4[q];
    }

    for (int it = 0; it < ntile; it++) {
        const int st = it & 1;
        {
            float* bs = (st ? Bs1 : Bs0) + row * PT + half * 16;
#pragma unroll
            for (int q = 0; q < 4; q++) {
                float4 v = bv[q];
                nb += v.x * v.x + v.y * v.y + v.z * v.z + v.w * v.w;
                *(float4*)(bs + q * 4) = v;
            }
        }
        if (it + 1 < ntile) {
            const float* src = aSrc + (size_t)(tile0 + it + 1) * BKA;
            uint32_t dstb = ((it + 1) & 1) ? asU1 : asU0;
#pragma unroll
            for (int q = 0; q < 4; q++) cpasync16(dstb + aOff + q * 16, src + q * 4);
        }
        CP_COMMIT();
        if (it + 1 < ntile) {
            const float4* bp4 = (const float4*)(bSrc + (size_t)(tile0 + it + 1) * BKA);
#pragma unroll
            for (int q = 0; q < 4; q++) bv[q] = bp4[q];
        }
        CP_WAIT1();
        __syncthreads();

        const float* as = st ? As1 : As0;
        const float* bs = st ? Bs1 : Bs0;
        if (bx == 0) {
            const float* ar = as + row * PT + half * 16;
#pragma unroll
            for (int q = 0; q < 16; q++) na += ar[q] * ar[q];
        }
#pragma unroll
        for (int k4 = 0; k4 < 8; k4++) {
            ulonglong2 a2[8];
#pragma unroll
            for (int i = 0; i < 8; i++)
                a2[i] = *(const ulonglong2*)(as + (ty + 16 * i) * PT + k4 * 4);
            ulonglong2 b2[4];
#pragma unroll
            for (int j = 0; j < 4; j++)
                b2[j] = *(const ulonglong2*)(bs + (tx + 16 * j) * PT + k4 * 4);
#pragma unroll
            for (int i = 0; i < 8; i++)
#pragma unroll
                for (int j = 0; j < 4; j++) ffma2(acc[i][j], a2[i].x, b2[j].x);
#pragma unroll
            for (int i = 0; i < 8; i++)
#pragma unroll
                for (int j = 0; j < 4; j++) ffma2(acc[i][j], a2[i].y, b2[j].y);
#pragma unroll
            for (int j = 0; j < 4; j++)
                b2[j] = *(const ulonglong2*)(bs + (tx + 16 * (j + 4)) * PT + k4 * 4);
#pragma unroll
            for (int i = 0; i < 8; i++)
#pragma unroll
                for (int j = 0; j < 4; j++) ffma2(acc[i][j + 4], a2[i].x, b2[j].x);
#pragma unroll
            for (int i = 0; i < 8; i++)
#pragma unroll
                for (int j = 0; j < 4; j++) ffma2(acc[i][j + 4], a2[i].y, b2[j].y);
        }
        __syncthreads();
    }

    nb += __shfl_xor_sync(0xFFFFFFFFu, nb, 1);
    if (half == 0) g_cnp[s][n0 + row] = nb;
    if (bx == 0) {
        na += __shfl_xor_sync(0xFFFFFFFFu, na, 1);
        if (half == 0) g_lnp[s][row] = na;
    }

    float* op = g_part[s];
#pragma unroll
    for (int i = 0; i < 8; i++) {
        const int m = ty + 16 * i;
#pragma unroll
        for (int j = 0; j < 8; j++) {
            float lo, hi;
            unpack2(acc[i][j], lo, hi);
            op[(size_t)m * C_SZ + n0 + tx + 16 * j] = lo + hi;
        }
    }
#endif
}

// ---------------------------------------------------------------------------
// Per-row: reduce partials (+ inline norm sums) -> dist, top-5 (lowest-index
// tie-break), softmax, outputs, usage scatter-add, stash for quantize.
// ---------------------------------------------------------------------------
__global__ void topk_kernel(float* __restrict__ out) {
    const int b   = blockIdx.x;
    const int tid = threadIdx.x;

    __shared__ float sd[C_SZ];
    __shared__ float rv[256];
    __shared__ int   ri[256];
    __shared__ float topd[TOPK];
    __shared__ int   topi[TOPK];
    __shared__ float s_ln;

    if (tid == 0) {
        float v = 0.f;
#pragma unroll
        for (int s = 0; s < SPLITS; s++) v += g_lnp[s][b];
        s_ln = v;
    }
    __syncthreads();
    const float ln = s_ln;

    for (int c = tid; c < C_SZ; c += 256) {
        float dot = 0.f, cn = 0.f;
#pragma unroll
        for (int s = 0; s < SPLITS; s++) {
            dot += g_part[s][b * C_SZ + c];
            cn  += g_cnp[s][c];
        }
        float d2 = ln + cn - 2.f * dot;
        sd[c] = sqrtf(fmaxf(d2, 0.f));
    }
    __syncthreads();

    for (int k = 0; k < TOPK; k++) {
        float best = FLT_MAX;
        int   bi   = C_SZ;
        for (int c = tid; c < C_SZ; c += 256) {
            float d = sd[c];
            if (d < best || (d == best && c < bi)) { best = d; bi = c; }
        }
        rv[tid] = best; ri[tid] = bi;
        __syncthreads();
        for (int s = 128; s > 0; s >>= 1) {
            if (tid < s) {
                float o = rv[tid + s]; int oi = ri[tid + s];
                if (o < rv[tid] || (o == rv[tid] && oi < ri[tid])) {
                    rv[tid] = o; ri[tid] = oi;
                }
            }
            __syncthreads();
        }
        if (tid == 0) {
            topd[k] = rv[0];
            topi[k] = ri[0];
            sd[ri[0]] = FLT_MAX;
        }
        __syncthreads();
    }

    if (tid == 0) {
        float m0 = topd[0];
        float e[TOPK], ssum = 0.f;
#pragma unroll
        for (int k = 0; k < TOPK; k++) {
            e[k] = expf(-(topd[k] - m0) / TEMP);
            ssum += e[k];
        }
        float inv = 1.f / ssum;
        out[OFF_IDX  + b] = (float)topi[0];
        out[OFF_DIST + b] = topd[0];
#pragma unroll
        for (int k = 0; k < TOPK; k++) {
            float w = e[k] * inv;
            atomicAdd(&out[OFF_USAGE + topi[k]], w);
            g_topw[b][k] = w;
            g_topi[b][k] = topi[k];
        }
    }
}

// ---------------------------------------------------------------------------
// quantized[b] = sum_k w[b][k] * codebook[idx[b][k]]   grid (B, 16 chunks)
// ---------------------------------------------------------------------------
__global__ void quant_kernel(const float* __restrict__ codebook,
                             float* __restrict__ out) {
    const int b     = blockIdx.x;
    const int chunk = blockIdx.y;
    const int tid   = threadIdx.x;
    __shared__ int   si[TOPK];
    __shared__ float sw[TOPK];
    if (tid < TOPK) { si[tid] = g_topi[b][tid]; sw[tid] = g_topw[b][tid]; }
    __syncthreads();

    const float4* cb = (const float4*)codebook;
    float4* outq = (float4*)(out + OFF_Q) + (size_t)b * D4;

    const float4* r0 = cb + (size_t)si[0] * D4;
    const float4* r1 = cb + (size_t)si[1] * D4;
    const float4* r2 = cb + (size_t)si[2] * D4;
    const float4* r3 = cb + (size_t)si[3] * D4;
    const float4* r4 = cb + (size_t)si[4] * D4;
    const float w0 = sw[0], w1 = sw[1], w2 = sw[2], w3 = sw[3], w4 = sw[4];

    const int p0 = chunk * (D4 / 16);
    const int p1 = p0 + (D4 / 16);
    for (int p = p0 + tid; p < p1; p += 256) {
        float4 v0 = r0[p], v1 = r1[p], v2 = r2[p], v3 = r3[p], v4 = r4[p];
        float4 r;
        r.x = w0 * v0.x + w1 * v1.x + w2 * v2.x + w3 * v3.x + w4 * v4.x;
        r.y = w0 * v0.y + w1 * v1.y + w2 * v2.y + w3 * v3.y + w4 * v4.y;
        r.z = w0 * v0.z + w1 * v1.z + w2 * v2.z + w3 * v3.z + w4 * v4.z;
        r.w = w0 * v0.w + w1 * v1.w + w2 * v2.w + w3 * v3.w + w4 * v4.w;
        outq[p] = r;
    }
}

// ---------------------------------------------------------------------------
extern "C" void kernel_launch(void* const* d_in, const int* in_sizes, int n_in,
                              void* d_out, int out_size) {
    const float* latent   = (const float*)d_in[0];
    const float* codebook = (const float*)d_in[1];
    const float* usage    = (const float*)d_in[2];
    float* out = (float*)d_out;

    cudaFuncSetAttribute((const void*)gemm_kernel,
                         cudaFuncAttributeMaxDynamicSharedMemorySize, DYN_SMEM);
    gemm_kernel<<<dim3(NB, SPLITS), 256, DYN_SMEM>>>(latent, codebook,
                                                     usage, out + OFF_USAGE);
    topk_kernel<<<B_SZ, 256>>>(out);
    quant_kernel<<<dim3(B_SZ, 16), 256>>>(codebook, out);
}